// round 5
// baseline (speedup 1.0000x reference)
#include <cuda_runtime.h>
#include <cstdint>

#define BATCH 20
#define SEQ   4096
#define EMB   256
#define NB    32
#define BLK   128
#define CTX   384
#define MROWS (BATCH*SEQ)

#define SA 36      // A smem stride (floats): bank = 4*g + tig, conflict-free
#define SB 136     // B smem stride (floats): bank = 8*tig + n, conflict-free
#define SMEMB ((2*128*SA + 2*32*SB) * 4)   // 71680 bytes

// Scratch (device globals; no allocations allowed)
__device__ float g_xc[MROWS*EMB];                 // x rounded to tf32
__device__ float g_wc[4*EMB*EMB];                 // Wq,Wk,Wv,Wo rounded to tf32
__device__ float g_q [MROWS*EMB];
__device__ float g_kT[MROWS*EMB];                 // K transposed per block: [blk][emb][token]
__device__ float g_v [MROWS*EMB];
__device__ float g_p [(size_t)BATCH*NB*BLK*CTX];
__device__ float g_att[MROWS*EMB];

// ---- primitives -----------------------------------------------------------

__device__ __forceinline__ uint32_t smem_u32(const void* p) {
    uint32_t a;
    asm("{ .reg .u64 t; cvta.to.shared.u64 t, %1; cvt.u32.u64 %0, t; }"
        : "=r"(a) : "l"(p));
    return a;
}

__device__ __forceinline__ float totf(float x) {
    uint32_t r;
    asm("cvt.rna.tf32.f32 %0, %1;" : "=r"(r) : "f"(x));
    return __uint_as_float(r);
}

__device__ __forceinline__ void cpa16(uint32_t dst, const float* src) {
    asm volatile("cp.async.cg.shared.global [%0], [%1], 16;" :: "r"(dst), "l"(src));
}
#define CP_COMMIT() asm volatile("cp.async.commit_group;" ::: "memory")
#define CP_WAIT1()  asm volatile("cp.async.wait_group 1;" ::: "memory")
#define CP_WAIT0()  asm volatile("cp.async.wait_group 0;" ::: "memory")

__device__ __forceinline__ void mma8(float c[4], float a0, float a1, float a2, float a3,
                                     float b0, float b1) {
    asm volatile(
        "mma.sync.aligned.m16n8k8.row.col.f32.tf32.tf32.f32 "
        "{%0,%1,%2,%3}, {%4,%5,%6,%7}, {%8,%9}, {%0,%1,%2,%3};"
        : "+f"(c[0]), "+f"(c[1]), "+f"(c[2]), "+f"(c[3])
        : "r"(__float_as_uint(a0)), "r"(__float_as_uint(a1)),
          "r"(__float_as_uint(a2)), "r"(__float_as_uint(a3)),
          "r"(__float_as_uint(b0)), "r"(__float_as_uint(b1)));
}

// ---- chunk copies (A: 128 rows x 32 k; B: 32 k x 128 n) -------------------

__device__ __forceinline__ void cpA(uint32_t sA, const float* __restrict__ src,
                                    int ld, int t) {
#pragma unroll
    for (int j = 0; j < 4; j++) {
        int idx = j * 256 + t;
        int m = idx >> 3, k4 = (idx & 7) << 2;
        cpa16(sA + (uint32_t)(m * SA + k4) * 4, src + (size_t)m * ld + k4);
    }
}

__device__ __forceinline__ void cpB(uint32_t sB, const float* __restrict__ src,
                                    int ld, int t) {
#pragma unroll
    for (int j = 0; j < 4; j++) {
        int idx = j * 256 + t;
        int k = idx >> 5, n4 = (idx & 31) << 2;
        cpa16(sB + (uint32_t)(k * SB + n4) * 4, src + (size_t)k * ld + n4);
    }
}

// ---- warp-tile compute for one 32-deep K chunk ----------------------------

__device__ __forceinline__ void mma_chunk(const float* __restrict__ As,
                                          const float* __restrict__ Bs,
                                          float acc[16][4], int t) {
    int lane = t & 31, w = t >> 5;
    int g = lane >> 2, tig = lane & 3;
    int mbase = (w >> 2) * 64 + g;
    int nbase = (w & 3) * 32 + g;
#pragma unroll
    for (int s = 0; s < 4; s++) {
        int k = s * 8 + tig;
        float b[4][2];
#pragma unroll
        for (int nt = 0; nt < 4; nt++) {
            b[nt][0] = Bs[k * SB + nbase + nt * 8];
            b[nt][1] = Bs[(k + 4) * SB + nbase + nt * 8];
        }
#pragma unroll
        for (int mt = 0; mt < 4; mt++) {
            int m = mbase + mt * 16;
            float a0 = As[m * SA + k];
            float a1 = As[(m + 8) * SA + k];
            float a2 = As[m * SA + k + 4];
            float a3 = As[(m + 8) * SA + k + 4];
#pragma unroll
            for (int nt = 0; nt < 4; nt++)
                mma8(acc[mt * 4 + nt], a0, a1, a2, a3, b[nt][0], b[nt][1]);
        }
    }
}

// ---- double-buffered pipeline over nC chunks ------------------------------

__device__ __forceinline__ void gemm_pipeline(const float* const* aS, const float* const* bS,
                                              int nC, int lda, int ldb,
                                              float acc[16][4], char* smem, int t) {
    float* A0 = (float*)smem;
    float* A1 = A0 + 128 * SA;
    float* B0 = A1 + 128 * SA;
    float* B1 = B0 + 32 * SB;
    float* Ab[2] = {A0, A1};
    float* Bb[2] = {B0, B1};
    uint32_t aAddr[2] = {smem_u32(A0), smem_u32(A1)};
    uint32_t bAddr[2] = {smem_u32(B0), smem_u32(B1)};

    cpA(aAddr[0], aS[0], lda, t);
    cpB(bAddr[0], bS[0], ldb, t);
    CP_COMMIT();

    for (int c = 0; c < nC; c++) {
        if (c + 1 < nC) {
            cpA(aAddr[(c + 1) & 1], aS[c + 1], lda, t);
            cpB(bAddr[(c + 1) & 1], bS[c + 1], ldb, t);
            CP_COMMIT();
            CP_WAIT1();
        } else {
            CP_WAIT0();
        }
        __syncthreads();
        mma_chunk(Ab[c & 1], Bb[c & 1], acc, t);
        __syncthreads();
    }
}

// ---- standard epilogue ----------------------------------------------------

__device__ __forceinline__ void store_std(float acc[16][4], float* __restrict__ C, int ldc,
                                          float scale, const float* __restrict__ bias,
                                          bool rnd, int t) {
    int lane = t & 31, w = t >> 5;
    int g = lane >> 2, tig = lane & 3;
    int mbase = (w >> 2) * 64 + g;
    int nbase = (w & 3) * 32 + 2 * tig;
#pragma unroll
    for (int mt = 0; mt < 4; mt++) {
#pragma unroll
        for (int nt = 0; nt < 4; nt++) {
            float* c4 = acc[mt * 4 + nt];
            int m = mbase + mt * 16, n = nbase + nt * 8;
            float v0 = c4[0] * scale, v1 = c4[1] * scale;
            float v2 = c4[2] * scale, v3 = c4[3] * scale;
            if (bias) { v0 += bias[n]; v1 += bias[n + 1]; v2 += bias[n]; v3 += bias[n + 1]; }
            if (rnd) { v0 = totf(v0); v1 = totf(v1); v2 = totf(v2); v3 = totf(v3); }
            *(float2*)(C + (size_t)m * ldc + n)       = make_float2(v0, v1);
            *(float2*)(C + (size_t)(m + 8) * ldc + n) = make_float2(v2, v3);
        }
    }
}

// ---- kernel: pre-convert to tf32 ------------------------------------------

__global__ __launch_bounds__(256)
void cvt_kernel(const float* __restrict__ src, float* __restrict__ dst, int n4) {
    int i = blockIdx.x * 256 + threadIdx.x;
    if (i < n4) {
        float4 v = ((const float4*)src)[i];
        v.x = totf(v.x); v.y = totf(v.y); v.z = totf(v.z); v.w = totf(v.w);
        ((float4*)dst)[i] = v;
    }
}

// ---- kernel 1: QKV projections --------------------------------------------

__global__ __launch_bounds__(256)
void qkv_mma() {
    extern __shared__ char smbuf[];
    int t = threadIdx.x;
    int z = blockIdx.z;
    int m0 = blockIdx.x * 128, n0 = blockIdx.y * 128;
    const float* W = g_wc + (size_t)z * EMB * EMB;

    const float* aS[8];
    const float* bS[8];
#pragma unroll
    for (int c = 0; c < 8; c++) {
        aS[c] = g_xc + (size_t)m0 * EMB + c * 32;
        bS[c] = W + (size_t)(c * 32) * EMB + n0;
    }
    float acc[16][4] = {};
    gemm_pipeline(aS, bS, 8, EMB, EMB, acc, smbuf, t);

    if (z == 1) {
        // transposed store: g_kT[m0*256 + (n0+n)*128 + m] = tf32(C[m][n])
        float* KT = g_kT + (size_t)m0 * EMB + (size_t)n0 * 128;
        int lane = t & 31, w = t >> 5;
        int g = lane >> 2, tig = lane & 3;
        int mbase = (w >> 2) * 64 + g;
        int nbase = (w & 3) * 32 + 2 * tig;
#pragma unroll
        for (int mt = 0; mt < 4; mt++) {
#pragma unroll
            for (int nt = 0; nt < 4; nt++) {
                float* c4 = acc[mt * 4 + nt];
                int m = mbase + mt * 16, n = nbase + nt * 8;
                KT[(size_t)n * 128 + m]           = totf(c4[0]);
                KT[(size_t)(n + 1) * 128 + m]     = totf(c4[1]);
                KT[(size_t)n * 128 + m + 8]       = totf(c4[2]);
                KT[(size_t)(n + 1) * 128 + m + 8] = totf(c4[3]);
            }
        }
    } else {
        float* C = (z == 0 ? g_q : g_v) + (size_t)m0 * EMB + n0;
        store_std(acc, C, EMB, 1.0f, nullptr, true, t);
    }
}

// ---- kernel 2: logits = Q @ K^T / 16 --------------------------------------

__global__ __launch_bounds__(256)
void qk_mma() {
    extern __shared__ char smbuf[];
    int t = threadIdx.x;
    int cj = blockIdx.x, nbi = blockIdx.y, b = blockIdx.z;
    int gb = nbi + cj - 1;
    float* P = g_p + ((size_t)(b * NB + nbi) * BLK) * CTX + cj * BLK;

    if (gb < 0 || gb >= NB) {
        for (int i = t; i < 128 * 32; i += 256) {
            int m = i >> 5, n4 = (i & 31) * 4;
            *(float4*)(P + (size_t)m * CTX + n4) = make_float4(0.f, 0.f, 0.f, 0.f);
        }
        return;
    }

    const float* Q  = g_q + (size_t)(b * SEQ + nbi * BLK) * EMB;
    const float* KT = g_kT + (size_t)(b * SEQ + gb * BLK) * EMB;   // [256 e][128 tok]

    const float* aS[8];
    const float* bS[8];
#pragma unroll
    for (int c = 0; c < 8; c++) {
        aS[c] = Q + c * 32;
        bS[c] = KT + (size_t)(c * 32) * 128;
    }
    float acc[16][4] = {};
    gemm_pipeline(aS, bS, 8, EMB, 128, acc, smbuf, t);
    store_std(acc, P, CTX, 0.0625f, nullptr, false, t);
}

// ---- kernel 3: softmax over 384-wide context (tf32-rounded store) ---------

__global__ __launch_bounds__(256)
void softmax_kernel() {
    int row = blockIdx.x * 8 + (threadIdx.x >> 5);
    int lane = threadIdx.x & 31;
    float* p = g_p + (size_t)row * CTX;

    float v[12];
#pragma unroll
    for (int i = 0; i < 12; i++) v[i] = p[lane + i * 32];
    float m = v[0];
#pragma unroll
    for (int i = 1; i < 12; i++) m = fmaxf(m, v[i]);
#pragma unroll
    for (int off = 16; off > 0; off >>= 1)
        m = fmaxf(m, __shfl_xor_sync(0xFFFFFFFFu, m, off));
    float s = 0.f;
#pragma unroll
    for (int i = 0; i < 12; i++) { v[i] = __expf(v[i] - m); s += v[i]; }
#pragma unroll
    for (int off = 16; off > 0; off >>= 1)
        s += __shfl_xor_sync(0xFFFFFFFFu, s, off);
    float inv = 1.f / s;
#pragma unroll
    for (int i = 0; i < 12; i++) p[lane + i * 32] = totf(v[i] * inv);
}

// ---- kernel 4: O = P @ Vc, permuted store ---------------------------------

__global__ __launch_bounds__(256)
void av_mma() {
    extern __shared__ char smbuf[];
    int t = threadIdx.x;
    int nt = blockIdx.x, nbi = blockIdx.y, b = blockIdx.z;
    int n0 = nt * 128;
    const float* Pb = g_p + (size_t)((b * NB + nbi) * BLK) * CTX;

    const float* aS[12];
    const float* bS[12];
    int nC = 0;
    for (int cb = 0; cb < 3; cb++) {
        int gb = nbi + cb - 1;
        if (gb < 0 || gb >= NB) continue;
        for (int kc = 0; kc < 4; kc++) {
            aS[nC] = Pb + cb * 128 + kc * 32;
            bS[nC] = g_v + (size_t)(b * SEQ + gb * BLK + kc * 32) * EMB + n0;
            nC++;
        }
    }
    float acc[16][4] = {};
    gemm_pipeline(aS, bS, nC, CTX, EMB, acc, smbuf, t);

    int rowbase = nbi * (BATCH * BLK) + b * BLK;   // reference transpose (1,0,2,3)
    store_std(acc, g_att + (size_t)rowbase * EMB + n0, EMB, 1.0f, nullptr, true, t);
}

// ---- kernel 5: out = att @ Wo + bo ----------------------------------------

__global__ __launch_bounds__(256)
void out_mma(const float* __restrict__ bo, float* __restrict__ out) {
    extern __shared__ char smbuf[];
    int t = threadIdx.x;
    int m0 = blockIdx.x * 128, n0 = blockIdx.y * 128;
    const float* W = g_wc + (size_t)3 * EMB * EMB;

    const float* aS[8];
    const float* bS[8];
#pragma unroll
    for (int c = 0; c < 8; c++) {
        aS[c] = g_att + (size_t)m0 * EMB + c * 32;
        bS[c] = W + (size_t)(c * 32) * EMB + n0;
    }
    float acc[16][4] = {};
    gemm_pipeline(aS, bS, 8, EMB, EMB, acc, smbuf, t);
    store_std(acc, out + (size_t)m0 * EMB + n0, EMB, 1.0f, bo + n0, false, t);
}

// ---- launch ---------------------------------------------------------------

extern "C" void kernel_launch(void* const* d_in, const int* in_sizes, int n_in,
                              void* d_out, int out_size) {
    const float* x  = (const float*)d_in[0];
    const float* Wq = (const float*)d_in[1];
    const float* Wk = (const float*)d_in[2];
    const float* Wv = (const float*)d_in[3];
    const float* Wo = (const float*)d_in[4];
    const float* bo = (const float*)d_in[5];
    float* out = (float*)d_out;

    cudaFuncSetAttribute(qkv_mma, cudaFuncAttributeMaxDynamicSharedMemorySize, SMEMB);
    cudaFuncSetAttribute(qk_mma,  cudaFuncAttributeMaxDynamicSharedMemorySize, SMEMB);
    cudaFuncSetAttribute(av_mma,  cudaFuncAttributeMaxDynamicSharedMemorySize, SMEMB);
    cudaFuncSetAttribute(out_mma, cudaFuncAttributeMaxDynamicSharedMemorySize, SMEMB);

    float* xc = nullptr; float* wc = nullptr;
    cudaGetSymbolAddress((void**)&xc, g_xc);
    cudaGetSymbolAddress((void**)&wc, g_wc);

    cvt_kernel<<<(MROWS * EMB / 4 + 255) / 256, 256>>>(x, xc, MROWS * EMB / 4);
    cvt_kernel<<<(EMB * EMB / 4 + 255) / 256, 256>>>(Wq, wc + 0 * EMB * EMB, EMB * EMB / 4);
    cvt_kernel<<<(EMB * EMB / 4 + 255) / 256, 256>>>(Wk, wc + 1 * EMB * EMB, EMB * EMB / 4);
    cvt_kernel<<<(EMB * EMB / 4 + 255) / 256, 256>>>(Wv, wc + 2 * EMB * EMB, EMB * EMB / 4);
    cvt_kernel<<<(EMB * EMB / 4 + 255) / 256, 256>>>(Wo, wc + 3 * EMB * EMB, EMB * EMB / 4);

    qkv_mma<<<dim3(MROWS / 128, EMB / 128, 3), 256, SMEMB>>>();
    qk_mma<<<dim3(3, NB, BATCH), 256, SMEMB>>>();
    softmax_kernel<<<(MROWS / 8), 256>>>();
    av_mma<<<dim3(2, NB, BATCH), 256, SMEMB>>>();
    out_mma<<<dim3(MROWS / 128, EMB / 128), 256, SMEMB>>>(bo, out);
}

// round 6
// speedup vs baseline: 1.0423x; 1.0423x over previous
#include <cuda_runtime.h>
#include <cstdint>

#define BATCH 20
#define SEQ   4096
#define EMB   256
#define NB    32
#define BLK   128
#define CTX   384
#define MROWS (BATCH*SEQ)

#define SA 36      // A smem stride (floats): conflict-free
#define SB 136     // B smem stride (floats): conflict-free
#define ABUF (128*SA*4)            // 18432 B per A stage
#define BBUF (32*SB*4)             // 17408 B per B stage
#define SMEMB (3*ABUF + 3*BBUF + 512)   // 108032 B (3-stage + 128-float l_s)

// Scratch (device globals; no allocations allowed)
__device__ float g_xc[MROWS*EMB];
__device__ float g_wc[4*EMB*EMB];
__device__ float g_q [MROWS*EMB];
__device__ float g_kT[MROWS*EMB];                 // K transposed per block: [blk][emb][token]
__device__ float g_v [MROWS*EMB];
__device__ float g_p [(size_t)BATCH*NB*BLK*CTX];  // exp(logits)
__device__ float g_l [MROWS];                     // softmax row sums
__device__ float g_att[MROWS*EMB];

// ---- primitives -----------------------------------------------------------

__device__ __forceinline__ uint32_t smem_u32(const void* p) {
    uint32_t a;
    asm("{ .reg .u64 t; cvta.to.shared.u64 t, %1; cvt.u32.u64 %0, t; }"
        : "=r"(a) : "l"(p));
    return a;
}

__device__ __forceinline__ float totf(float x) {
    uint32_t r;
    asm("cvt.rna.tf32.f32 %0, %1;" : "=r"(r) : "f"(x));
    return __uint_as_float(r);
}

__device__ __forceinline__ void cpa16(uint32_t dst, const float* src) {
    asm volatile("cp.async.cg.shared.global [%0], [%1], 16;" :: "r"(dst), "l"(src));
}
#define CP_COMMIT() asm volatile("cp.async.commit_group;" ::: "memory")
#define CP_WAIT1()  asm volatile("cp.async.wait_group 1;" ::: "memory")
#define CP_WAIT0()  asm volatile("cp.async.wait_group 0;" ::: "memory")

__device__ __forceinline__ void mma8(float c[4], float a0, float a1, float a2, float a3,
                                     float b0, float b1) {
    asm volatile(
        "mma.sync.aligned.m16n8k8.row.col.f32.tf32.tf32.f32 "
        "{%0,%1,%2,%3}, {%4,%5,%6,%7}, {%8,%9}, {%0,%1,%2,%3};"
        : "+f"(c[0]), "+f"(c[1]), "+f"(c[2]), "+f"(c[3])
        : "r"(__float_as_uint(a0)), "r"(__float_as_uint(a1)),
          "r"(__float_as_uint(a2)), "r"(__float_as_uint(a3)),
          "r"(__float_as_uint(b0)), "r"(__float_as_uint(b1)));
}

// ---- chunk copies (A: 128 rows x 32 k; B: 32 k x 128 n) -------------------

__device__ __forceinline__ void cpA(uint32_t sA, const float* __restrict__ src,
                                    int ld, int t) {
#pragma unroll
    for (int j = 0; j < 4; j++) {
        int idx = j * 256 + t;
        int m = idx >> 3, k4 = (idx & 7) << 2;
        cpa16(sA + (uint32_t)(m * SA + k4) * 4, src + (size_t)m * ld + k4);
    }
}

__device__ __forceinline__ void cpB(uint32_t sB, const float* __restrict__ src,
                                    int ld, int t) {
#pragma unroll
    for (int j = 0; j < 4; j++) {
        int idx = j * 256 + t;
        int k = idx >> 5, n4 = (idx & 31) << 2;
        cpa16(sB + (uint32_t)(k * SB + n4) * 4, src + (size_t)k * ld + n4);
    }
}

// ---- warp-tile compute for one 32-deep K chunk ----------------------------

__device__ __forceinline__ void mma_chunk(const float* __restrict__ As,
                                          const float* __restrict__ Bs,
                                          float acc[16][4], int t) {
    int lane = t & 31, w = t >> 5;
    int g = lane >> 2, tig = lane & 3;
    int mbase = (w >> 2) * 64 + g;
    int nbase = (w & 3) * 32 + g;
#pragma unroll
    for (int s = 0; s < 4; s++) {
        int k = s * 8 + tig;
        float b[4][2];
#pragma unroll
        for (int nt = 0; nt < 4; nt++) {
            b[nt][0] = Bs[k * SB + nbase + nt * 8];
            b[nt][1] = Bs[(k + 4) * SB + nbase + nt * 8];
        }
#pragma unroll
        for (int mt = 0; mt < 4; mt++) {
            int m = mbase + mt * 16;
            float a0 = As[m * SA + k];
            float a1 = As[(m + 8) * SA + k];
            float a2 = As[m * SA + k + 4];
            float a3 = As[(m + 8) * SA + k + 4];
#pragma unroll
            for (int nt = 0; nt < 4; nt++)
                mma8(acc[mt * 4 + nt], a0, a1, a2, a3, b[nt][0], b[nt][1]);
        }
    }
}

// ---- 3-stage pipeline, one __syncthreads per chunk ------------------------
// chunk c: A at Abase + c*aStep, B at Bbase + c*bStep (affine; no ptr arrays)

__device__ __forceinline__ void gemm_pipeline(const float* __restrict__ Abase, int aStep, int lda,
                                              const float* __restrict__ Bbase, int bStep, int ldb,
                                              int nC, float acc[16][4], char* smem, int t) {
    uint32_t aA[3], bA[3];
    const float* Ap[3];
    const float* Bp[3];
#pragma unroll
    for (int i = 0; i < 3; i++) {
        Ap[i] = (const float*)(smem + i * ABUF);
        Bp[i] = (const float*)(smem + 3 * ABUF + i * BBUF);
        aA[i] = smem_u32(Ap[i]);
        bA[i] = smem_u32(Bp[i]);
    }
    cpA(aA[0], Abase, lda, t);
    cpB(bA[0], Bbase, ldb, t);
    CP_COMMIT();
    cpA(aA[1], Abase + aStep, lda, t);
    cpB(bA[1], Bbase + (size_t)bStep, ldb, t);
    CP_COMMIT();

    int bufc = 0, bufn = 2;
    for (int c = 0; c < nC; c++) {
        if (c < nC - 1) CP_WAIT1(); else CP_WAIT0();
        __syncthreads();
        if (c + 2 < nC) {
            cpA(aA[bufn], Abase + (size_t)(c + 2) * aStep, lda, t);
            cpB(bA[bufn], Bbase + (size_t)(c + 2) * bStep, ldb, t);
            CP_COMMIT();
        }
        mma_chunk(Ap[bufc], Bp[bufc], acc, t);
        bufc = (bufc == 2) ? 0 : bufc + 1;
        bufn = (bufn == 2) ? 0 : bufn + 1;
    }
}

// ---- standard epilogue ----------------------------------------------------

__device__ __forceinline__ void store_std(float acc[16][4], float* __restrict__ C, int ldc,
                                          const float* __restrict__ bias,
                                          bool rnd, int t) {
    int lane = t & 31, w = t >> 5;
    int g = lane >> 2, tig = lane & 3;
    int mbase = (w >> 2) * 64 + g;
    int nbase = (w & 3) * 32 + 2 * tig;
#pragma unroll
    for (int mt = 0; mt < 4; mt++) {
#pragma unroll
        for (int nt = 0; nt < 4; nt++) {
            float* c4 = acc[mt * 4 + nt];
            int m = mbase + mt * 16, n = nbase + nt * 8;
            float v0 = c4[0], v1 = c4[1], v2 = c4[2], v3 = c4[3];
            if (bias) { v0 += bias[n]; v1 += bias[n + 1]; v2 += bias[n]; v3 += bias[n + 1]; }
            if (rnd) { v0 = totf(v0); v1 = totf(v1); v2 = totf(v2); v3 = totf(v3); }
            *(float2*)(C + (size_t)m * ldc + n)       = make_float2(v0, v1);
            *(float2*)(C + (size_t)(m + 8) * ldc + n) = make_float2(v2, v3);
        }
    }
}

// ---- helper kernels -------------------------------------------------------

__global__ __launch_bounds__(256)
void cvt_kernel(const float* __restrict__ src, float* __restrict__ dst, int n4) {
    int i = blockIdx.x * 256 + threadIdx.x;
    if (i < n4) {
        float4 v = ((const float4*)src)[i];
        v.x = totf(v.x); v.y = totf(v.y); v.z = totf(v.z); v.w = totf(v.w);
        ((float4*)dst)[i] = v;
    }
}

// init row sums with the padded-context contribution: 128 * exp(0) per missing block
__global__ __launch_bounds__(256)
void linit_kernel() {
    int i = blockIdx.x * 256 + threadIdx.x;     // 81920 rows
    int nbi = (i >> 7) & (NB - 1);
    g_l[i] = 128.0f * (float)((nbi == 0) + (nbi == NB - 1));
}

// ---- kernel 1: QKV projections --------------------------------------------

__global__ __launch_bounds__(256, 2)
void qkv_mma() {
    extern __shared__ char smbuf[];
    int t = threadIdx.x;
    int z = blockIdx.z;
    int m0 = blockIdx.x * 128, n0 = blockIdx.y * 128;
    const float* W = g_wc + (size_t)z * EMB * EMB;

    float acc[16][4] = {};
    gemm_pipeline(g_xc + (size_t)m0 * EMB, 32, EMB,
                  W + n0, 32 * EMB, EMB, 8, acc, smbuf, t);

    if (z == 1) {
        // transposed store: g_kT[m0*256 + (n0+n)*128 + m] = tf32(C[m][n])
        float* KT = g_kT + (size_t)m0 * EMB + (size_t)n0 * 128;
        int lane = t & 31, w = t >> 5;
        int g = lane >> 2, tig = lane & 3;
        int mbase = (w >> 2) * 64 + g;
        int nbase = (w & 3) * 32 + 2 * tig;
#pragma unroll
        for (int mt = 0; mt < 4; mt++) {
#pragma unroll
            for (int nt = 0; nt < 4; nt++) {
                float* c4 = acc[mt * 4 + nt];
                int m = mbase + mt * 16, n = nbase + nt * 8;
                KT[(size_t)n * 128 + m]           = totf(c4[0]);
                KT[(size_t)(n + 1) * 128 + m]     = totf(c4[1]);
                KT[(size_t)n * 128 + m + 8]       = totf(c4[2]);
                KT[(size_t)(n + 1) * 128 + m + 8] = totf(c4[3]);
            }
        }
    } else {
        float* C = (z == 0 ? g_q : g_v) + (size_t)m0 * EMB + n0;
        store_std(acc, C, EMB, nullptr, true, t);
    }
}

// ---- kernel 2: P = exp(Q @ K^T / 16), row sums -> g_l ---------------------

__global__ __launch_bounds__(256, 2)
void qk_mma() {
    extern __shared__ char smbuf[];
    float* ls = (float*)(smbuf + 3 * ABUF + 3 * BBUF);
    int t = threadIdx.x;
    int cj = blockIdx.x, nbi = blockIdx.y, b = blockIdx.z;
    int gb = nbi + cj - 1;
    if (gb < 0 || gb >= NB) return;             // padded: handled by linit

    if (t < 128) ls[t] = 0.f;                   // covered by pipeline's first barrier

    const float* Q  = g_q  + (size_t)(b * SEQ + nbi * BLK) * EMB;
    const float* KT = g_kT + (size_t)(b * SEQ + gb * BLK) * EMB;   // [256 e][128 tok]

    float acc[16][4] = {};
    gemm_pipeline(Q, 32, EMB, KT, 32 * 128, 128, 8, acc, smbuf, t);

    // epilogue: e = exp(s/16); store; row-sum
    float* P = g_p + ((size_t)(b * NB + nbi) * BLK) * CTX + cj * BLK;
    int lane = t & 31, w = t >> 5;
    int g = lane >> 2, tig = lane & 3;
    int mbase = (w >> 2) * 64 + g;
    int nbase = (w & 3) * 32 + 2 * tig;
    float rsum[8];
#pragma unroll
    for (int i = 0; i < 8; i++) rsum[i] = 0.f;
#pragma unroll
    for (int mt = 0; mt < 4; mt++) {
#pragma unroll
        for (int nt = 0; nt < 4; nt++) {
            float* c4 = acc[mt * 4 + nt];
            int m = mbase + mt * 16, n = nbase + nt * 8;
            float e0 = __expf(c4[0] * 0.0625f);
            float e1 = __expf(c4[1] * 0.0625f);
            float e2 = __expf(c4[2] * 0.0625f);
            float e3 = __expf(c4[3] * 0.0625f);
            rsum[mt * 2 + 0] += e0 + e1;
            rsum[mt * 2 + 1] += e2 + e3;
            *(float2*)(P + (size_t)m * CTX + n)       = make_float2(totf(e0), totf(e1));
            *(float2*)(P + (size_t)(m + 8) * CTX + n) = make_float2(totf(e2), totf(e3));
        }
    }
    // reduce across the 4 threads-in-group (n coverage within warp)
#pragma unroll
    for (int i = 0; i < 8; i++) {
        rsum[i] += __shfl_xor_sync(0xFFFFFFFFu, rsum[i], 1);
        rsum[i] += __shfl_xor_sync(0xFFFFFFFFu, rsum[i], 2);
    }
    if (tig == 0) {
#pragma unroll
        for (int i = 0; i < 8; i++)
            atomicAdd(&ls[mbase + (i >> 1) * 16 + (i & 1) * 8], rsum[i]);
    }
    __syncthreads();
    if (t < 128)
        atomicAdd(&g_l[(size_t)(b * NB + nbi) * 128 + t], ls[t]);
}

// ---- kernel 3: O = (P @ Vc) / l, permuted store ---------------------------

__global__ __launch_bounds__(256, 2)
void av_mma() {
    extern __shared__ char smbuf[];
    int t = threadIdx.x;
    int nt0 = blockIdx.x, nbi = blockIdx.y, b = blockIdx.z;
    int n0 = nt0 * 128;

    int lo = (nbi == 0) ? 1 : 0;                 // first valid cb
    int hi = (nbi == NB - 1) ? 1 : 2;            // last valid cb
    int nC = (hi - lo + 1) * 4;
    int gb0 = nbi + lo - 1;

    const float* Pb = g_p + (size_t)((b * NB + nbi) * BLK) * CTX + lo * 128;
    const float* Vb = g_v + (size_t)(b * SEQ + gb0 * BLK) * EMB + n0;

    float acc[16][4] = {};
    gemm_pipeline(Pb, 32, CTX, Vb, 32 * EMB, EMB, nC, acc, smbuf, t);

    // divide by row sums, tf32-round, store with (nb,b) permutation
    const float* lrow = g_l + (size_t)(b * NB + nbi) * 128;
    int rowbase = nbi * (BATCH * BLK) + b * BLK;
    float* C = g_att + (size_t)rowbase * EMB + n0;

    int lane = t & 31, w = t >> 5;
    int g = lane >> 2, tig = lane & 3;
    int mbase = (w >> 2) * 64 + g;
    int nbase = (w & 3) * 32 + 2 * tig;
#pragma unroll
    for (int mt = 0; mt < 4; mt++) {
        int m = mbase + mt * 16;
        float inv0 = 1.0f / lrow[m];
        float inv1 = 1.0f / lrow[m + 8];
#pragma unroll
        for (int ntt = 0; ntt < 4; ntt++) {
            float* c4 = acc[mt * 4 + ntt];
            int n = nbase + ntt * 8;
            *(float2*)(C + (size_t)m * EMB + n) =
                make_float2(totf(c4[0] * inv0), totf(c4[1] * inv0));
            *(float2*)(C + (size_t)(m + 8) * EMB + n) =
                make_float2(totf(c4[2] * inv1), totf(c4[3] * inv1));
        }
    }
}

// ---- kernel 4: out = att @ Wo + bo ----------------------------------------

__global__ __launch_bounds__(256, 2)
void out_mma(const float* __restrict__ bo, float* __restrict__ out) {
    extern __shared__ char smbuf[];
    int t = threadIdx.x;
    int m0 = blockIdx.x * 128, n0 = blockIdx.y * 128;
    const float* W = g_wc + (size_t)3 * EMB * EMB;

    float acc[16][4] = {};
    gemm_pipeline(g_att + (size_t)m0 * EMB, 32, EMB,
                  W + n0, 32 * EMB, EMB, 8, acc, smbuf, t);
    store_std(acc, out + (size_t)m0 * EMB + n0, EMB, bo + n0, false, t);
}

// ---- launch ---------------------------------------------------------------

extern "C" void kernel_launch(void* const* d_in, const int* in_sizes, int n_in,
                              void* d_out, int out_size) {
    const float* x  = (const float*)d_in[0];
    const float* Wq = (const float*)d_in[1];
    const float* Wk = (const float*)d_in[2];
    const float* Wv = (const float*)d_in[3];
    const float* Wo = (const float*)d_in[4];
    const float* bo = (const float*)d_in[5];
    float* out = (float*)d_out;

    cudaFuncSetAttribute(qkv_mma, cudaFuncAttributeMaxDynamicSharedMemorySize, SMEMB);
    cudaFuncSetAttribute(qk_mma,  cudaFuncAttributeMaxDynamicSharedMemorySize, SMEMB);
    cudaFuncSetAttribute(av_mma,  cudaFuncAttributeMaxDynamicSharedMemorySize, SMEMB);
    cudaFuncSetAttribute(out_mma, cudaFuncAttributeMaxDynamicSharedMemorySize, SMEMB);

    float* xc = nullptr; float* wc = nullptr;
    cudaGetSymbolAddress((void**)&xc, g_xc);
    cudaGetSymbolAddress((void**)&wc, g_wc);

    cvt_kernel<<<(MROWS * EMB / 4 + 255) / 256, 256>>>(x, xc, MROWS * EMB / 4);
    cvt_kernel<<<(EMB * EMB / 4 + 255) / 256, 256>>>(Wq, wc + 0 * EMB * EMB, EMB * EMB / 4);
    cvt_kernel<<<(EMB * EMB / 4 + 255) / 256, 256>>>(Wk, wc + 1 * EMB * EMB, EMB * EMB / 4);
    cvt_kernel<<<(EMB * EMB / 4 + 255) / 256, 256>>>(Wv, wc + 2 * EMB * EMB, EMB * EMB / 4);
    cvt_kernel<<<(EMB * EMB / 4 + 255) / 256, 256>>>(Wo, wc + 3 * EMB * EMB, EMB * EMB / 4);
    linit_kernel<<<MROWS / 256, 256>>>();

    qkv_mma<<<dim3(MROWS / 128, EMB / 128, 3), 256, SMEMB>>>();
    qk_mma<<<dim3(3, NB, BATCH), 256, SMEMB>>>();
    av_mma<<<dim3(2, NB, BATCH), 256, SMEMB>>>();
    out_mma<<<dim3(MROWS / 128, EMB / 128), 256, SMEMB>>>(bo, out);
}